// round 13
// baseline (speedup 1.0000x reference)
#include <cuda_runtime.h>

#define FULLMASK 0xffffffffu
#define MAXN 16384

// Scratch (device globals — no allocation)
__device__ float g_G[MAXN * 128];   // G[j][tm] = x_j . tf_{t,m}
__device__ float g_xn2[MAXN];       // |x_j|^2
__device__ float g_tf2[128];        // |tf_{t,m}|^2
__device__ float g_C2s[128 * 8];    // symmetrized C2 rows

// ---------------- packed f32x2 + MUFU helpers ----------------
union f2u { float2 f; unsigned long long u; };
__device__ __forceinline__ float2 fma2(float2 a, float2 b, float2 c) {
    f2u A, B, C, D; A.f = a; B.f = b; C.f = c;
    asm("fma.rn.f32x2 %0, %1, %2, %3;" : "=l"(D.u) : "l"(A.u), "l"(B.u), "l"(C.u));
    return D.f;
}
__device__ __forceinline__ float2 mul2(float2 a, float2 b) {
    f2u A, B, D; A.f = a; B.f = b;
    asm("mul.rn.f32x2 %0, %1, %2;" : "=l"(D.u) : "l"(A.u), "l"(B.u));
    return D.f;
}
__device__ __forceinline__ float2 add2(float2 a, float2 b) {
    f2u A, B, D; A.f = a; B.f = b;
    asm("add.rn.f32x2 %0, %1, %2;" : "=l"(D.u) : "l"(A.u), "l"(B.u));
    return D.f;
}
__device__ __forceinline__ float ex2(float x) {
    float r; asm("ex2.approx.f32 %0, %1;" : "=f"(r) : "f"(x)); return r;
}
__device__ __forceinline__ float rcpf(float x) {
    float r; asm("rcp.approx.f32 %0, %1;" : "=f"(r) : "f"(x)); return r;
}
__device__ __forceinline__ float2 bc2(float s) { return make_float2(s, s); }

// ---------------- Kernel A: precompute (32 nodes/block) ----------------
__global__ void __launch_bounds__(128)
precompute_kernel(const float* __restrict__ x,
                  const float* __restrict__ lt,
                  const float* __restrict__ tf,
                  int N)
{
    __shared__ float xs[32][128];
    const int tid = threadIdx.x;
    const int n0  = blockIdx.x * 32;

    #pragma unroll
    for (int j = 0; j < 32; j++)
        xs[j][tid] = (n0 + j < N) ? __ldg(&x[(n0 + j) * 128 + tid]) : 0.f;
    __syncthreads();

    const float4* tfr = (const float4*)(tf + tid * 128);
    float acc[32];
    #pragma unroll
    for (int j = 0; j < 32; j++) acc[j] = 0.f;
    float tf2a = 0.f;
    #pragma unroll 1
    for (int c4 = 0; c4 < 32; c4++) {
        float4 tv = __ldg(&tfr[c4]);
        tf2a += tv.x*tv.x + tv.y*tv.y + tv.z*tv.z + tv.w*tv.w;
        #pragma unroll
        for (int j = 0; j < 32; j++) {
            float4 v = *(const float4*)&xs[j][c4 * 4];
            acc[j] += v.x*tv.x + v.y*tv.y + v.z*tv.z + v.w*tv.w;
        }
    }
    #pragma unroll
    for (int j = 0; j < 32; j++)
        if (n0 + j < N) g_G[(n0 + j) * 128 + tid] = acc[j];

    const int jn = tid >> 2, off = (tid & 3) * 32;
    float s = 0.f;
    #pragma unroll
    for (int k = 0; k < 32; k++) { float v = xs[jn][off + k]; s += v * v; }
    s += __shfl_xor_sync(FULLMASK, s, 1);
    s += __shfl_xor_sync(FULLMASK, s, 2);
    if ((tid & 3) == 0 && n0 + jn < N) g_xn2[n0 + jn] = s;

    if (blockIdx.x == 0) {
        g_tf2[tid] = tf2a;
        const int t = tid >> 3, m = tid & 7;
        #pragma unroll
        for (int l = 0; l < 8; l++)
            g_C2s[tid * 8 + l] = 0.5f * (__ldg(&lt[(t * 8 + m) * 8 + l]) +
                                         __ldg(&lt[(t * 8 + l) * 8 + m]));
    }
}

// +EKC*A for the star graph, 2-lane groups. K holds P.
// c2l points at this thread's 4 C2 rows (EKC-scaled) in block-shared memory.
__device__ __forceinline__ void compute_pA(
    const float2 K[9][4], const float2* __restrict__ c2l,
    int l, int mate_src,
    float2 pA0f[4], float2 pArf[4])
{
    float2 s2[4], p02[4];
    #pragma unroll
    for (int c = 0; c < 4; c++) {
        float2 a = (l == 0) ? bc2(0.f) : K[0][c];
        float2 b = add2(K[1][c], K[2][c]);
        a = add2(a, add2(K[3][c], K[4][c]));
        b = add2(b, add2(K[5][c], K[6][c]));
        a = add2(a, add2(K[7][c], K[8][c]));
        a = add2(a, b);
        a.x += __shfl_xor_sync(FULLMASK, a.x, 1);
        a.y += __shfl_xor_sync(FULLMASK, a.y, 1);
        s2[c] = a;
        p02[c].x = __shfl_sync(FULLMASK, K[0][c].x, mate_src);
        p02[c].y = __shfl_sync(FULLMASK, K[0][c].y, mate_src);
    }
    float osA[4], osP[4];
    #pragma unroll
    for (int j = 0; j < 4; j++) {
        float2 c2 = c2l[j * 4 + 0];
        float2 aA = mul2(s2[0], c2);
        float2 aP = mul2(p02[0], c2);
        #pragma unroll
        for (int c = 1; c < 4; c++) {
            c2 = c2l[j * 4 + c];
            aA = fma2(s2[c],  c2, aA);
            aP = fma2(p02[c], c2, aP);
        }
        osA[j] = aA.x + aA.y;
        osP[j] = aP.x + aP.y;
    }
    float2 oA0 = make_float2(osA[0], osA[1]), oA1 = make_float2(osA[2], osA[3]);
    float2 oP0 = make_float2(osP[0], osP[1]), oP1 = make_float2(osP[2], osP[3]);
    float2 mA0, mA1, mP0, mP1;
    mA0.x = __shfl_xor_sync(FULLMASK, oA0.x, 1); mA0.y = __shfl_xor_sync(FULLMASK, oA0.y, 1);
    mA1.x = __shfl_xor_sync(FULLMASK, oA1.x, 1); mA1.y = __shfl_xor_sync(FULLMASK, oA1.y, 1);
    mP0.x = __shfl_xor_sync(FULLMASK, oP0.x, 1); mP0.y = __shfl_xor_sync(FULLMASK, oP0.y, 1);
    mP1.x = __shfl_xor_sync(FULLMASK, oP1.x, 1); mP1.y = __shfl_xor_sync(FULLMASK, oP1.y, 1);
    bool li = (l != 0);
    pA0f[0] = li ? mA0 : oA0; pA0f[1] = li ? mA1 : oA1;
    pA0f[2] = li ? oA0 : mA0; pA0f[3] = li ? oA1 : mA1;
    pArf[0] = li ? mP0 : oP0; pArf[1] = li ? mP1 : oP1;
    pArf[2] = li ? oP0 : mP0; pArf[3] = li ? oP1 : mP1;
}

// ---------------- Kernel B: FGW, 2 lanes per (node,template) ----------------
__global__ void __launch_bounds__(64, 9)
otgnn_fgw_kernel(const int* __restrict__ dst,
                 const float* __restrict__ Wm,
                 const float* __restrict__ bvec,
                 float* __restrict__ out)
{
    __shared__ float2 eMh_s[32][64];   // ex2(Mhn) rowsets 0..7, thread-private
    __shared__ float2 eMh8_s[4][32];   // rowset 8 (row 16), per (warp, template)
    __shared__ float2 C2sh[16 * 33];   // EKC-scaled C2, per template (stride 33)
    __shared__ int   idxs[2][17];
    __shared__ float xn2s[2][17];
    __shared__ float fgw_s[2][16];

    const int tid  = threadIdx.x;
    const int w    = tid >> 5;
    const int lane = tid & 31;
    const int node = blockIdx.x * 2 + w;
    const int t    = lane >> 1;
    const int l    = lane & 1;
    const int mate_src = lane & ~1;
    const bool l0 = (l == 0);

    if (lane < 17) {
        int id = lane ? __ldg(&dst[node * 16 + lane - 1]) : node;
        idxs[w][lane] = id;
        xn2s[w][lane] = g_xn2[id];
    }
    __syncwarp();

    const float EKC = 7.21347520444482f;   // 5 * log2(e)
    const float HF  = -0.5f * EKC;
    const float2 ONE = bc2(1.f);

    // Own C2 rows 4l..4l+3; cc2; write EKC-scaled C2 once per block (warp 0)
    {
        float2 C2h[4][4];
        #pragma unroll
        for (int j = 0; j < 4; j++) {
            const float4* p = (const float4*)&g_C2s[(t * 8 + 4 * l + j) * 8];
            float4 a = __ldg(&p[0]), b = __ldg(&p[1]);
            C2h[j][0] = make_float2(a.x, a.y); C2h[j][1] = make_float2(a.z, a.w);
            C2h[j][2] = make_float2(b.x, b.y); C2h[j][3] = make_float2(b.z, b.w);
        }
        float2 cc2f[4];
        #pragma unroll
        for (int c = 0; c < 4; c++) {
            float2 a = mul2(C2h[0][c], C2h[0][c]);
            a = fma2(C2h[1][c], C2h[1][c], a);
            a = fma2(C2h[2][c], C2h[2][c], a);
            a = fma2(C2h[3][c], C2h[3][c], a);
            a.x += __shfl_xor_sync(FULLMASK, a.x, 1);
            a.y += __shfl_xor_sync(FULLMASK, a.y, 1);
            cc2f[c] = make_float2(a.x * 0.125f, a.y * 0.125f);
        }
        if (w == 0) {
            #pragma unroll
            for (int j = 0; j < 4; j++)
                #pragma unroll
                for (int c = 0; c < 4; c++)
                    C2sh[t * 33 + (4 * l + j) * 4 + c] = mul2(C2h[j][c], bc2(EKC));
        }

        // eMh = ex2(Mhn), Mhn = -(M + c1h + cc2) * 0.5 * EKC
        float2 tf2f[4];
        float4 ta = *(const float4*)&g_tf2[t * 8];
        float4 tb = *(const float4*)&g_tf2[t * 8 + 4];
        tf2f[0] = make_float2(ta.x, ta.y); tf2f[1] = make_float2(ta.z, ta.w);
        tf2f[2] = make_float2(tb.x, tb.y); tf2f[3] = make_float2(tb.z, tb.w);
        #pragma unroll
        for (int r = 0; r < 9; r++) {
            int row = (r < 8) ? 2 * r + l : 16;
            int id = idxs[w][row];
            float n2 = xn2s[w][row];
            float4 g0 = __ldg((const float4*)&g_G[id * 128 + t * 8]);
            float4 g1 = __ldg((const float4*)&g_G[id * 128 + t * 8 + 4]);
            float gg[8] = {g0.x,g0.y,g0.z,g0.w,g1.x,g1.y,g1.z,g1.w};
            float c1h = (r == 0 && l0) ? (16.f / 17.f) : (1.f / 17.f);
            #pragma unroll
            for (int c = 0; c < 4; c++) {
                float mx = (n2 + tf2f[c].x - 2.f * gg[2*c])   * (1.f / 128.f);
                float my = (n2 + tf2f[c].y - 2.f * gg[2*c+1]) * (1.f / 128.f);
                float2 e = make_float2(ex2((mx + c1h + cc2f[c].x) * HF),
                                       ex2((my + c1h + cc2f[c].y) * HF));
                if (r < 8) eMh_s[r * 4 + c][tid] = e;
                else if (l0) eMh8_s[c][w * 16 + t] = e;
            }
        }
    }
    __syncthreads();

    const float2* __restrict__ c2l  = &C2sh[t * 33 + l * 16];
    const float2* __restrict__ emh  = &eMh_s[0][tid];       // stride 64 slots
    const float2* __restrict__ emh8 = &eMh8_s[0][w * 16 + t]; // stride 32

    // State
    float2 K[9][4], vr[4];
    float u[9];
    #pragma unroll
    for (int r = 0; r < 9; r++) {
        float init = (r == 8) ? (l0 ? 1.f / 136.f : 0.f) : (1.f / 136.f);
        #pragma unroll
        for (int c = 0; c < 4; c++) K[r][c] = bc2(init);
        u[r] = 1.f;
    }
    #pragma unroll
    for (int c = 0; c < 4; c++) vr[c] = ONE;

    #pragma unroll 1
    for (int outer = 0; outer < 5; outer++) {
        // P in place: K <- u * K * v
        #pragma unroll
        for (int r = 0; r < 9; r++) {
            float2 uf = bc2(u[r]);
            #pragma unroll
            for (int c = 0; c < 4; c++) K[r][c] = mul2(mul2(K[r][c], vr[c]), uf);
        }
        float2 pA0f[4], pArf[4];
        compute_pA(K, c2l, l, mate_src, pA0f, pArf);

        // K <- P * eMh * (row0 ratio); column scale absorbed into v-init
        #pragma unroll
        for (int c = 0; c < 4; c++) {
            float2 epr, rfx;
            epr.x = ex2(pArf[c].x);
            epr.y = ex2(pArf[c].y);
            rfx.x = ex2(pA0f[c].x - pArf[c].x);
            rfx.y = ex2(pA0f[c].y - pArf[c].y);
            if (!l0) rfx = ONE;
            K[0][c] = mul2(mul2(K[0][c], emh[c * 64]), rfx);
            #pragma unroll
            for (int r = 1; r < 8; r++)
                K[r][c] = mul2(K[r][c], emh[(r * 4 + c) * 64]);
            K[8][c] = mul2(K[8][c], emh8[c * 32]);   // lane1: 0 * x = 0
            vr[c] = epr;
        }

        // Sinkhorn. Epsilon ONLY on r==8 (lane 1's zero row -> rcp(0)=inf).
        #pragma unroll 1
        for (int inner = 0; inner < 10; inner++) {
            #pragma unroll
            for (int r = 0; r < 9; r++) {
                float2 d0 = mul2(K[r][0], vr[0]);
                float2 d1 = mul2(K[r][1], vr[1]);
                d0 = fma2(K[r][2], vr[2], d0);
                d1 = fma2(K[r][3], vr[3], d1);
                d0 = add2(d0, d1);
                float den = d0.x + d0.y;
                if (r == 8) den += 1e-30f;
                u[r] = rcpf(den);
            }
            #pragma unroll
            for (int c = 0; c < 4; c++) {
                float2 pa = mul2(K[0][c], bc2(u[0]));
                float2 pb = mul2(K[1][c], bc2(u[1]));
                float2 pc = mul2(K[2][c], bc2(u[2]));
                pa = fma2(K[3][c], bc2(u[3]), pa);
                pb = fma2(K[4][c], bc2(u[4]), pb);
                pc = fma2(K[5][c], bc2(u[5]), pc);
                pa = fma2(K[6][c], bc2(u[6]), pa);
                pb = fma2(K[7][c], bc2(u[7]), pb);
                pc = fma2(K[8][c], bc2(u[8]), pc);
                pa = add2(pa, add2(pb, pc));
                pa.x += __shfl_xor_sync(FULLMASK, pa.x, 1);
                pa.y += __shfl_xor_sync(FULLMASK, pa.y, 1);
                vr[c].x = rcpf(pa.x);
                vr[c].y = rcpf(pa.y);
            }
        }
        #pragma unroll
        for (int r = 0; r < 9; r++) u[r] *= 0.125f;
    }

    // ---- Final: P in place, recompute Mhn, fgw = -(1/EKC) sum((Mhn+pA).*P) ----
    #pragma unroll
    for (int r = 0; r < 9; r++) {
        float2 uf = bc2(u[r]);
        #pragma unroll
        for (int c = 0; c < 4; c++) K[r][c] = mul2(mul2(K[r][c], vr[c]), uf);
    }
    {
        float2 pA0f[4], pArf[4];
        compute_pA(K, c2l, l, mate_src, pA0f, pArf);

        // cc2 from EKC-scaled C2sh: (1/8)/EKC^2 * sum over all 8 rows
        float2 cc2f[4];
        const float CSC = 0.125f / (EKC * EKC);
        #pragma unroll
        for (int c = 0; c < 4; c++) {
            float2 a = mul2(c2l[c], c2l[c]);
            a = fma2(c2l[4 + c],  c2l[4 + c],  a);
            a = fma2(c2l[8 + c],  c2l[8 + c],  a);
            a = fma2(c2l[12 + c], c2l[12 + c], a);
            a.x += __shfl_xor_sync(FULLMASK, a.x, 1);
            a.y += __shfl_xor_sync(FULLMASK, a.y, 1);
            cc2f[c] = make_float2(a.x * CSC, a.y * CSC);
        }
        float2 tf2f[4];
        float4 ta = *(const float4*)&g_tf2[t * 8];
        float4 tb = *(const float4*)&g_tf2[t * 8 + 4];
        tf2f[0] = make_float2(ta.x, ta.y); tf2f[1] = make_float2(ta.z, ta.w);
        tf2f[2] = make_float2(tb.x, tb.y); tf2f[3] = make_float2(tb.z, tb.w);

        float2 accv = bc2(0.f);
        #pragma unroll
        for (int r = 0; r < 9; r++) {
            int row = (r < 8) ? 2 * r + l : 16;
            int id = idxs[w][row];
            float n2 = xn2s[w][row];
            float4 g0 = __ldg((const float4*)&g_G[id * 128 + t * 8]);
            float4 g1 = __ldg((const float4*)&g_G[id * 128 + t * 8 + 4]);
            float gg[8] = {g0.x,g0.y,g0.z,g0.w,g1.x,g1.y,g1.z,g1.w};
            float c1h = (r == 0 && l0) ? (16.f / 17.f) : (1.f / 17.f);
            const float2* pa = (r == 0 && l0) ? pA0f : pArf;
            #pragma unroll
            for (int c = 0; c < 4; c++) {
                float mx = (n2 + tf2f[c].x - 2.f * gg[2*c])   * (1.f / 128.f);
                float my = (n2 + tf2f[c].y - 2.f * gg[2*c+1]) * (1.f / 128.f);
                float2 g = make_float2((mx + c1h + cc2f[c].x) * HF + pa[c].x,
                                       (my + c1h + cc2f[c].y) * HF + pa[c].y);
                accv = fma2(g, K[r][c], accv);
            }
        }
        float loc = accv.x + accv.y;
        loc += __shfl_xor_sync(FULLMASK, loc, 1);
        if (l0) fgw_s[w][t] = loc * (-1.f / EKC);
    }
    __syncwarp();

    if (lane < 8) {
        float o = __ldg(&bvec[lane]);
        #pragma unroll
        for (int tt = 0; tt < 16; tt++)
            o += fgw_s[w][tt] * __ldg(&Wm[tt * 8 + lane]);
        out[node * 8 + lane] = o;
    }
}

extern "C" void kernel_launch(void* const* d_in, const int* in_sizes, int n_in,
                              void* d_out, int out_size) {
    const float* x   = (const float*)d_in[0];
    const int*   ei  = (const int*)d_in[1];
    const float* lt  = (const float*)d_in[2];
    const float* tf  = (const float*)d_in[3];
    const float* Wm  = (const float*)d_in[4];
    const float* bv  = (const float*)d_in[5];
    float* out = (float*)d_out;

    const int N = in_sizes[0] / 128;   // 10000 (even)
    const int* dst = ei + N * 16;

    precompute_kernel<<<(N + 31) / 32, 128>>>(x, lt, tf, N);
    otgnn_fgw_kernel<<<N / 2, 64>>>(dst, Wm, bv, out);
}

// round 14
// speedup vs baseline: 1.0451x; 1.0451x over previous
#include <cuda_runtime.h>

#define FULLMASK 0xffffffffu
#define MAXN 16384

// Scratch (device globals — no allocation)
__device__ float g_G[MAXN * 128];   // G[j][tm] = x_j . tf_{t,m}
__device__ float g_xn2[MAXN];       // |x_j|^2
__device__ float g_tf2[128];        // |tf_{t,m}|^2
__device__ float g_C2s[128 * 8];    // symmetrized C2 rows

// ---------------- packed f32x2 + MUFU helpers ----------------
union f2u { float2 f; unsigned long long u; };
__device__ __forceinline__ float2 fma2(float2 a, float2 b, float2 c) {
    f2u A, B, C, D; A.f = a; B.f = b; C.f = c;
    asm("fma.rn.f32x2 %0, %1, %2, %3;" : "=l"(D.u) : "l"(A.u), "l"(B.u), "l"(C.u));
    return D.f;
}
__device__ __forceinline__ float2 mul2(float2 a, float2 b) {
    f2u A, B, D; A.f = a; B.f = b;
    asm("mul.rn.f32x2 %0, %1, %2;" : "=l"(D.u) : "l"(A.u), "l"(B.u));
    return D.f;
}
__device__ __forceinline__ float2 add2(float2 a, float2 b) {
    f2u A, B, D; A.f = a; B.f = b;
    asm("add.rn.f32x2 %0, %1, %2;" : "=l"(D.u) : "l"(A.u), "l"(B.u));
    return D.f;
}
__device__ __forceinline__ float ex2(float x) {
    float r; asm("ex2.approx.f32 %0, %1;" : "=f"(r) : "f"(x)); return r;
}
__device__ __forceinline__ float rcpf(float x) {
    float r; asm("rcp.approx.f32 %0, %1;" : "=f"(r) : "f"(x)); return r;
}
__device__ __forceinline__ float2 bc2(float s) { return make_float2(s, s); }

// ---------------- Kernel A: precompute (32 nodes/block, f32x2) ----------------
__global__ void __launch_bounds__(128)
precompute_kernel(const float* __restrict__ x,
                  const float* __restrict__ lt,
                  const float* __restrict__ tf,
                  int N)
{
    __shared__ float xs[32][128];
    const int tid = threadIdx.x;
    const int n0  = blockIdx.x * 32;

    #pragma unroll
    for (int j = 0; j < 32; j++)
        xs[j][tid] = (n0 + j < N) ? __ldg(&x[(n0 + j) * 128 + tid]) : 0.f;
    __syncthreads();

    const float4* tfr = (const float4*)(tf + tid * 128);
    float2 acc[32];
    #pragma unroll
    for (int j = 0; j < 32; j++) acc[j] = bc2(0.f);
    float2 tf2p = bc2(0.f);
    #pragma unroll 1
    for (int c4 = 0; c4 < 32; c4++) {
        float4 tv = __ldg(&tfr[c4]);
        float2 tva = make_float2(tv.x, tv.y);
        float2 tvb = make_float2(tv.z, tv.w);
        tf2p = fma2(tva, tva, tf2p);
        tf2p = fma2(tvb, tvb, tf2p);
        #pragma unroll
        for (int j = 0; j < 32; j++) {
            float4 v = *(const float4*)&xs[j][c4 * 4];
            float2 va = make_float2(v.x, v.y);
            float2 vb = make_float2(v.z, v.w);
            acc[j] = fma2(va, tva, acc[j]);
            acc[j] = fma2(vb, tvb, acc[j]);
        }
    }
    #pragma unroll
    for (int j = 0; j < 32; j++)
        if (n0 + j < N) g_G[(n0 + j) * 128 + tid] = acc[j].x + acc[j].y;

    const int jn = tid >> 2, off = (tid & 3) * 32;
    float2 sp = bc2(0.f);
    #pragma unroll
    for (int k = 0; k < 16; k++) {
        float2 v = *(const float2*)&xs[jn][off + 2 * k];
        sp = fma2(v, v, sp);
    }
    float s = sp.x + sp.y;
    s += __shfl_xor_sync(FULLMASK, s, 1);
    s += __shfl_xor_sync(FULLMASK, s, 2);
    if ((tid & 3) == 0 && n0 + jn < N) g_xn2[n0 + jn] = s;

    if (blockIdx.x == 0) {
        g_tf2[tid] = tf2p.x + tf2p.y;
        const int t = tid >> 3, m = tid & 7;
        #pragma unroll
        for (int l = 0; l < 8; l++)
            g_C2s[tid * 8 + l] = 0.5f * (__ldg(&lt[(t * 8 + m) * 8 + l]) +
                                         __ldg(&lt[(t * 8 + l) * 8 + m]));
    }
}

// +EKC*A for the star graph, 2-lane groups. K holds P.
// c2l points at this thread's 4 C2 rows (EKC-scaled) in block-shared memory.
__device__ __forceinline__ void compute_pA(
    const float2 K[9][4], const float2* __restrict__ c2l,
    int l, int mate_src,
    float2 pA0f[4], float2 pArf[4])
{
    float2 s2[4], p02[4];
    #pragma unroll
    for (int c = 0; c < 4; c++) {
        float2 a = (l == 0) ? bc2(0.f) : K[0][c];
        float2 b = add2(K[1][c], K[2][c]);
        a = add2(a, add2(K[3][c], K[4][c]));
        b = add2(b, add2(K[5][c], K[6][c]));
        a = add2(a, add2(K[7][c], K[8][c]));
        a = add2(a, b);
        a.x += __shfl_xor_sync(FULLMASK, a.x, 1);
        a.y += __shfl_xor_sync(FULLMASK, a.y, 1);
        s2[c] = a;
        p02[c].x = __shfl_sync(FULLMASK, K[0][c].x, mate_src);
        p02[c].y = __shfl_sync(FULLMASK, K[0][c].y, mate_src);
    }
    float osA[4], osP[4];
    #pragma unroll
    for (int j = 0; j < 4; j++) {
        float2 c2 = c2l[j * 4 + 0];
        float2 aA = mul2(s2[0], c2);
        float2 aP = mul2(p02[0], c2);
        #pragma unroll
        for (int c = 1; c < 4; c++) {
            c2 = c2l[j * 4 + c];
            aA = fma2(s2[c],  c2, aA);
            aP = fma2(p02[c], c2, aP);
        }
        osA[j] = aA.x + aA.y;
        osP[j] = aP.x + aP.y;
    }
    float2 oA0 = make_float2(osA[0], osA[1]), oA1 = make_float2(osA[2], osA[3]);
    float2 oP0 = make_float2(osP[0], osP[1]), oP1 = make_float2(osP[2], osP[3]);
    float2 mA0, mA1, mP0, mP1;
    mA0.x = __shfl_xor_sync(FULLMASK, oA0.x, 1); mA0.y = __shfl_xor_sync(FULLMASK, oA0.y, 1);
    mA1.x = __shfl_xor_sync(FULLMASK, oA1.x, 1); mA1.y = __shfl_xor_sync(FULLMASK, oA1.y, 1);
    mP0.x = __shfl_xor_sync(FULLMASK, oP0.x, 1); mP0.y = __shfl_xor_sync(FULLMASK, oP0.y, 1);
    mP1.x = __shfl_xor_sync(FULLMASK, oP1.x, 1); mP1.y = __shfl_xor_sync(FULLMASK, oP1.y, 1);
    bool li = (l != 0);
    pA0f[0] = li ? mA0 : oA0; pA0f[1] = li ? mA1 : oA1;
    pA0f[2] = li ? oA0 : mA0; pA0f[3] = li ? oA1 : mA1;
    pArf[0] = li ? mP0 : oP0; pArf[1] = li ? mP1 : oP1;
    pArf[2] = li ? oP0 : mP0; pArf[3] = li ? oP1 : mP1;
}

// ---------------- Kernel B: FGW, 2 lanes per (node,template) ----------------
__global__ void __launch_bounds__(64, 8)
otgnn_fgw_kernel(const int* __restrict__ dst,
                 const float* __restrict__ Wm,
                 const float* __restrict__ bvec,
                 float* __restrict__ out)
{
    __shared__ float2 eMh_s[32][64];   // ex2(Mhn) rowsets 0..7, thread-private
    __shared__ float2 eMh8_s[4][32];   // rowset 8 (row 16), per (warp, template)
    __shared__ float2 C2sh[16 * 33];   // EKC-scaled C2, per template (stride 33)
    __shared__ int   idxs[2][17];
    __shared__ float xn2s[2][17];
    __shared__ float fgw_s[2][16];

    const int tid  = threadIdx.x;
    const int w    = tid >> 5;
    const int lane = tid & 31;
    const int node = blockIdx.x * 2 + w;
    const int t    = lane >> 1;
    const int l    = lane & 1;
    const int mate_src = lane & ~1;
    const bool l0 = (l == 0);

    if (lane < 17) {
        int id = lane ? __ldg(&dst[node * 16 + lane - 1]) : node;
        idxs[w][lane] = id;
        xn2s[w][lane] = g_xn2[id];
    }
    __syncwarp();

    const float EKC = 7.21347520444482f;   // 5 * log2(e)
    const float HF  = -0.5f * EKC;
    const float2 ONE = bc2(1.f);

    // Own C2 rows 4l..4l+3; cc2; write EKC-scaled C2 once per block (warp 0)
    {
        float2 C2h[4][4];
        #pragma unroll
        for (int j = 0; j < 4; j++) {
            const float4* p = (const float4*)&g_C2s[(t * 8 + 4 * l + j) * 8];
            float4 a = __ldg(&p[0]), b = __ldg(&p[1]);
            C2h[j][0] = make_float2(a.x, a.y); C2h[j][1] = make_float2(a.z, a.w);
            C2h[j][2] = make_float2(b.x, b.y); C2h[j][3] = make_float2(b.z, b.w);
        }
        float2 cc2f[4];
        #pragma unroll
        for (int c = 0; c < 4; c++) {
            float2 a = mul2(C2h[0][c], C2h[0][c]);
            a = fma2(C2h[1][c], C2h[1][c], a);
            a = fma2(C2h[2][c], C2h[2][c], a);
            a = fma2(C2h[3][c], C2h[3][c], a);
            a.x += __shfl_xor_sync(FULLMASK, a.x, 1);
            a.y += __shfl_xor_sync(FULLMASK, a.y, 1);
            cc2f[c] = make_float2(a.x * 0.125f, a.y * 0.125f);
        }
        if (w == 0) {
            #pragma unroll
            for (int j = 0; j < 4; j++)
                #pragma unroll
                for (int c = 0; c < 4; c++)
                    C2sh[t * 33 + (4 * l + j) * 4 + c] = mul2(C2h[j][c], bc2(EKC));
        }

        // eMh = ex2(Mhn), Mhn = -(M + c1h + cc2) * 0.5 * EKC
        float2 tf2f[4];
        float4 ta = *(const float4*)&g_tf2[t * 8];
        float4 tb = *(const float4*)&g_tf2[t * 8 + 4];
        tf2f[0] = make_float2(ta.x, ta.y); tf2f[1] = make_float2(ta.z, ta.w);
        tf2f[2] = make_float2(tb.x, tb.y); tf2f[3] = make_float2(tb.z, tb.w);
        #pragma unroll
        for (int r = 0; r < 9; r++) {
            int row = (r < 8) ? 2 * r + l : 16;
            int id = idxs[w][row];
            float n2 = xn2s[w][row];
            float4 g0 = __ldg((const float4*)&g_G[id * 128 + t * 8]);
            float4 g1 = __ldg((const float4*)&g_G[id * 128 + t * 8 + 4]);
            float gg[8] = {g0.x,g0.y,g0.z,g0.w,g1.x,g1.y,g1.z,g1.w};
            float c1h = (r == 0 && l0) ? (16.f / 17.f) : (1.f / 17.f);
            #pragma unroll
            for (int c = 0; c < 4; c++) {
                float mx = (n2 + tf2f[c].x - 2.f * gg[2*c])   * (1.f / 128.f);
                float my = (n2 + tf2f[c].y - 2.f * gg[2*c+1]) * (1.f / 128.f);
                float2 e = make_float2(ex2((mx + c1h + cc2f[c].x) * HF),
                                       ex2((my + c1h + cc2f[c].y) * HF));
                if (r < 8) eMh_s[r * 4 + c][tid] = e;
                else if (l0) eMh8_s[c][w * 16 + t] = e;
            }
        }
    }
    __syncthreads();

    const float2* __restrict__ c2l  = &C2sh[t * 33 + l * 16];
    const float2* __restrict__ emh  = &eMh_s[0][tid];         // stride 64 slots
    const float2* __restrict__ emh8 = &eMh8_s[0][w * 16 + t]; // stride 32

    // State
    float2 K[9][4], vr[4];
    float u[9];
    #pragma unroll
    for (int r = 0; r < 9; r++) {
        float init = (r == 8) ? (l0 ? 1.f / 136.f : 0.f) : (1.f / 136.f);
        #pragma unroll
        for (int c = 0; c < 4; c++) K[r][c] = bc2(init);
        u[r] = 1.f;
    }
    #pragma unroll
    for (int c = 0; c < 4; c++) vr[c] = ONE;

    #pragma unroll 1
    for (int outer = 0; outer < 5; outer++) {
        // P in place: K <- u * K * v
        #pragma unroll
        for (int r = 0; r < 9; r++) {
            float2 uf = bc2(u[r]);
            #pragma unroll
            for (int c = 0; c < 4; c++) K[r][c] = mul2(mul2(K[r][c], vr[c]), uf);
        }
        float2 pA0f[4], pArf[4];
        compute_pA(K, c2l, l, mate_src, pA0f, pArf);

        // K <- P * eMh * (row0 ratio); column scale absorbed into v-init
        #pragma unroll
        for (int c = 0; c < 4; c++) {
            float2 epr, rfx;
            epr.x = ex2(pArf[c].x);
            epr.y = ex2(pArf[c].y);
            rfx.x = ex2(pA0f[c].x - pArf[c].x);
            rfx.y = ex2(pA0f[c].y - pArf[c].y);
            if (!l0) rfx = ONE;
            K[0][c] = mul2(mul2(K[0][c], emh[c * 64]), rfx);
            #pragma unroll
            for (int r = 1; r < 8; r++)
                K[r][c] = mul2(K[r][c], emh[(r * 4 + c) * 64]);
            K[8][c] = mul2(K[8][c], emh8[c * 32]);   // lane1: 0 * x = 0
            vr[c] = epr;
        }

        // Sinkhorn. Epsilon ONLY on r==8 (lane 1's zero row -> rcp(0)=inf).
        #pragma unroll 1
        for (int inner = 0; inner < 10; inner++) {
            #pragma unroll
            for (int r = 0; r < 9; r++) {
                float2 d0 = mul2(K[r][0], vr[0]);
                float2 d1 = mul2(K[r][1], vr[1]);
                d0 = fma2(K[r][2], vr[2], d0);
                d1 = fma2(K[r][3], vr[3], d1);
                d0 = add2(d0, d1);
                float den = d0.x + d0.y;
                if (r == 8) den += 1e-30f;
                u[r] = rcpf(den);
            }
            #pragma unroll
            for (int c = 0; c < 4; c++) {
                float2 pa = mul2(K[0][c], bc2(u[0]));
                float2 pb = mul2(K[1][c], bc2(u[1]));
                float2 pc = mul2(K[2][c], bc2(u[2]));
                pa = fma2(K[3][c], bc2(u[3]), pa);
                pb = fma2(K[4][c], bc2(u[4]), pb);
                pc = fma2(K[5][c], bc2(u[5]), pc);
                pa = fma2(K[6][c], bc2(u[6]), pa);
                pb = fma2(K[7][c], bc2(u[7]), pb);
                pc = fma2(K[8][c], bc2(u[8]), pc);
                pa = add2(pa, add2(pb, pc));
                pa.x += __shfl_xor_sync(FULLMASK, pa.x, 1);
                pa.y += __shfl_xor_sync(FULLMASK, pa.y, 1);
                vr[c].x = rcpf(pa.x);
                vr[c].y = rcpf(pa.y);
            }
        }
        #pragma unroll
        for (int r = 0; r < 9; r++) u[r] *= 0.125f;
    }

    // ---- Final: P in place, recompute Mhn, fgw = -(1/EKC) sum((Mhn+pA).*P) ----
    #pragma unroll
    for (int r = 0; r < 9; r++) {
        float2 uf = bc2(u[r]);
        #pragma unroll
        for (int c = 0; c < 4; c++) K[r][c] = mul2(mul2(K[r][c], vr[c]), uf);
    }
    {
        float2 pA0f[4], pArf[4];
        compute_pA(K, c2l, l, mate_src, pA0f, pArf);

        // cc2 from EKC-scaled C2sh: (1/8)/EKC^2 * sum over all 8 rows
        float2 cc2f[4];
        const float CSC = 0.125f / (EKC * EKC);
        #pragma unroll
        for (int c = 0; c < 4; c++) {
            float2 a = mul2(c2l[c], c2l[c]);
            a = fma2(c2l[4 + c],  c2l[4 + c],  a);
            a = fma2(c2l[8 + c],  c2l[8 + c],  a);
            a = fma2(c2l[12 + c], c2l[12 + c], a);
            a.x += __shfl_xor_sync(FULLMASK, a.x, 1);
            a.y += __shfl_xor_sync(FULLMASK, a.y, 1);
            cc2f[c] = make_float2(a.x * CSC, a.y * CSC);
        }
        float2 tf2f[4];
        float4 ta = *(const float4*)&g_tf2[t * 8];
        float4 tb = *(const float4*)&g_tf2[t * 8 + 4];
        tf2f[0] = make_float2(ta.x, ta.y); tf2f[1] = make_float2(ta.z, ta.w);
        tf2f[2] = make_float2(tb.x, tb.y); tf2f[3] = make_float2(tb.z, tb.w);

        float2 accv = bc2(0.f);
        #pragma unroll
        for (int r = 0; r < 9; r++) {
            int row = (r < 8) ? 2 * r + l : 16;
            int id = idxs[w][row];
            float n2 = xn2s[w][row];
            float4 g0 = __ldg((const float4*)&g_G[id * 128 + t * 8]);
            float4 g1 = __ldg((const float4*)&g_G[id * 128 + t * 8 + 4]);
            float gg[8] = {g0.x,g0.y,g0.z,g0.w,g1.x,g1.y,g1.z,g1.w};
            float c1h = (r == 0 && l0) ? (16.f / 17.f) : (1.f / 17.f);
            const float2* pa = (r == 0 && l0) ? pA0f : pArf;
            #pragma unroll
            for (int c = 0; c < 4; c++) {
                float mx = (n2 + tf2f[c].x - 2.f * gg[2*c])   * (1.f / 128.f);
                float my = (n2 + tf2f[c].y - 2.f * gg[2*c+1]) * (1.f / 128.f);
                float2 g = make_float2((mx + c1h + cc2f[c].x) * HF + pa[c].x,
                                       (my + c1h + cc2f[c].y) * HF + pa[c].y);
                accv = fma2(g, K[r][c], accv);
            }
        }
        float loc = accv.x + accv.y;
        loc += __shfl_xor_sync(FULLMASK, loc, 1);
        if (l0) fgw_s[w][t] = loc * (-1.f / EKC);
    }
    __syncwarp();

    if (lane < 8) {
        float o = __ldg(&bvec[lane]);
        #pragma unroll
        for (int tt = 0; tt < 16; tt++)
            o += fgw_s[w][tt] * __ldg(&Wm[tt * 8 + lane]);
        out[node * 8 + lane] = o;
    }
}

extern "C" void kernel_launch(void* const* d_in, const int* in_sizes, int n_in,
                              void* d_out, int out_size) {
    const float* x   = (const float*)d_in[0];
    const int*   ei  = (const int*)d_in[1];
    const float* lt  = (const float*)d_in[2];
    const float* tf  = (const float*)d_in[3];
    const float* Wm  = (const float*)d_in[4];
    const float* bv  = (const float*)d_in[5];
    float* out = (float*)d_out;

    const int N = in_sizes[0] / 128;   // 10000 (even)
    const int* dst = ei + N * 16;

    precompute_kernel<<<(N + 31) / 32, 128>>>(x, lt, tf, N);
    otgnn_fgw_kernel<<<N / 2, 64>>>(dst, Wm, bv, out);
}

// round 15
// speedup vs baseline: 1.0617x; 1.0159x over previous
#include <cuda_runtime.h>

#define FULLMASK 0xffffffffu
#define MAXN 16384

// Scratch (device globals — no allocation)
__device__ float g_G[MAXN * 128];   // G[j][tm] = x_j . tf_{t,m}
__device__ float g_xn2[MAXN];       // |x_j|^2
__device__ float g_tf2[128];        // |tf_{t,m}|^2
__device__ float g_C2s[128 * 8];    // symmetrized C2 rows

// ---------------- packed f32x2 + MUFU helpers ----------------
union f2u { float2 f; unsigned long long u; };
__device__ __forceinline__ float2 fma2(float2 a, float2 b, float2 c) {
    f2u A, B, C, D; A.f = a; B.f = b; C.f = c;
    asm("fma.rn.f32x2 %0, %1, %2, %3;" : "=l"(D.u) : "l"(A.u), "l"(B.u), "l"(C.u));
    return D.f;
}
__device__ __forceinline__ float2 mul2(float2 a, float2 b) {
    f2u A, B, D; A.f = a; B.f = b;
    asm("mul.rn.f32x2 %0, %1, %2;" : "=l"(D.u) : "l"(A.u), "l"(B.u));
    return D.f;
}
__device__ __forceinline__ float2 add2(float2 a, float2 b) {
    f2u A, B, D; A.f = a; B.f = b;
    asm("add.rn.f32x2 %0, %1, %2;" : "=l"(D.u) : "l"(A.u), "l"(B.u));
    return D.f;
}
__device__ __forceinline__ float ex2(float x) {
    float r; asm("ex2.approx.f32 %0, %1;" : "=f"(r) : "f"(x)); return r;
}
__device__ __forceinline__ float rcpf(float x) {
    float r; asm("rcp.approx.f32 %0, %1;" : "=f"(r) : "f"(x)); return r;
}
__device__ __forceinline__ float2 bc2(float s) { return make_float2(s, s); }

// ---------------- Kernel A: precompute (32 nodes/block, f32x2) ----------------
__global__ void __launch_bounds__(128)
precompute_kernel(const float* __restrict__ x,
                  const float* __restrict__ lt,
                  const float* __restrict__ tf,
                  int N)
{
    __shared__ float xs[32][128];
    const int tid = threadIdx.x;
    const int n0  = blockIdx.x * 32;

    #pragma unroll
    for (int j = 0; j < 32; j++)
        xs[j][tid] = (n0 + j < N) ? __ldg(&x[(n0 + j) * 128 + tid]) : 0.f;
    __syncthreads();

    const float4* tfr = (const float4*)(tf + tid * 128);
    float2 acc[32];
    #pragma unroll
    for (int j = 0; j < 32; j++) acc[j] = bc2(0.f);
    float2 tf2p = bc2(0.f);
    #pragma unroll 1
    for (int c4 = 0; c4 < 32; c4++) {
        float4 tv = __ldg(&tfr[c4]);
        float2 tva = make_float2(tv.x, tv.y);
        float2 tvb = make_float2(tv.z, tv.w);
        tf2p = fma2(tva, tva, tf2p);
        tf2p = fma2(tvb, tvb, tf2p);
        #pragma unroll
        for (int j = 0; j < 32; j++) {
            float4 v = *(const float4*)&xs[j][c4 * 4];
            float2 va = make_float2(v.x, v.y);
            float2 vb = make_float2(v.z, v.w);
            acc[j] = fma2(va, tva, acc[j]);
            acc[j] = fma2(vb, tvb, acc[j]);
        }
    }
    #pragma unroll
    for (int j = 0; j < 32; j++)
        if (n0 + j < N) g_G[(n0 + j) * 128 + tid] = acc[j].x + acc[j].y;

    const int jn = tid >> 2, off = (tid & 3) * 32;
    float2 sp = bc2(0.f);
    #pragma unroll
    for (int k = 0; k < 16; k++) {
        float2 v = *(const float2*)&xs[jn][off + 2 * k];
        sp = fma2(v, v, sp);
    }
    float s = sp.x + sp.y;
    s += __shfl_xor_sync(FULLMASK, s, 1);
    s += __shfl_xor_sync(FULLMASK, s, 2);
    if ((tid & 3) == 0 && n0 + jn < N) g_xn2[n0 + jn] = s;

    if (blockIdx.x == 0) {
        g_tf2[tid] = tf2p.x + tf2p.y;
        const int t = tid >> 3, m = tid & 7;
        #pragma unroll
        for (int l = 0; l < 8; l++)
            g_C2s[tid * 8 + l] = 0.5f * (__ldg(&lt[(t * 8 + m) * 8 + l]) +
                                         __ldg(&lt[(t * 8 + l) * 8 + m]));
    }
}

// +EKC*A for the star graph, 2-lane groups. K holds P.
// c2l points at this thread's 4 C2 rows (EKC-scaled) in block-shared memory.
__device__ __forceinline__ void compute_pA(
    const float2 K[9][4], const float2* __restrict__ c2l,
    int l, int mate_src,
    float2 pA0f[4], float2 pArf[4])
{
    float2 s2[4], p02[4];
    #pragma unroll
    for (int c = 0; c < 4; c++) {
        float2 a = (l == 0) ? bc2(0.f) : K[0][c];
        float2 b = add2(K[1][c], K[2][c]);
        a = add2(a, add2(K[3][c], K[4][c]));
        b = add2(b, add2(K[5][c], K[6][c]));
        a = add2(a, add2(K[7][c], K[8][c]));
        a = add2(a, b);
        a.x += __shfl_xor_sync(FULLMASK, a.x, 1);
        a.y += __shfl_xor_sync(FULLMASK, a.y, 1);
        s2[c] = a;
        p02[c].x = __shfl_sync(FULLMASK, K[0][c].x, mate_src);
        p02[c].y = __shfl_sync(FULLMASK, K[0][c].y, mate_src);
    }
    float osA[4], osP[4];
    #pragma unroll
    for (int j = 0; j < 4; j++) {
        float2 c2 = c2l[j * 4 + 0];
        float2 aA = mul2(s2[0], c2);
        float2 aP = mul2(p02[0], c2);
        #pragma unroll
        for (int c = 1; c < 4; c++) {
            c2 = c2l[j * 4 + c];
            aA = fma2(s2[c],  c2, aA);
            aP = fma2(p02[c], c2, aP);
        }
        osA[j] = aA.x + aA.y;
        osP[j] = aP.x + aP.y;
    }
    float2 oA0 = make_float2(osA[0], osA[1]), oA1 = make_float2(osA[2], osA[3]);
    float2 oP0 = make_float2(osP[0], osP[1]), oP1 = make_float2(osP[2], osP[3]);
    float2 mA0, mA1, mP0, mP1;
    mA0.x = __shfl_xor_sync(FULLMASK, oA0.x, 1); mA0.y = __shfl_xor_sync(FULLMASK, oA0.y, 1);
    mA1.x = __shfl_xor_sync(FULLMASK, oA1.x, 1); mA1.y = __shfl_xor_sync(FULLMASK, oA1.y, 1);
    mP0.x = __shfl_xor_sync(FULLMASK, oP0.x, 1); mP0.y = __shfl_xor_sync(FULLMASK, oP0.y, 1);
    mP1.x = __shfl_xor_sync(FULLMASK, oP1.x, 1); mP1.y = __shfl_xor_sync(FULLMASK, oP1.y, 1);
    bool li = (l != 0);
    pA0f[0] = li ? mA0 : oA0; pA0f[1] = li ? mA1 : oA1;
    pA0f[2] = li ? oA0 : mA0; pA0f[3] = li ? oA1 : mA1;
    pArf[0] = li ? mP0 : oP0; pArf[1] = li ? mP1 : oP1;
    pArf[2] = li ? oP0 : mP0; pArf[3] = li ? oP1 : mP1;
}

// ---------------- Kernel B: FGW, 2 lanes per (node,template) ----------------
__global__ void __launch_bounds__(64, 8)
otgnn_fgw_kernel(const int* __restrict__ dst,
                 const float* __restrict__ Wm,
                 const float* __restrict__ bvec,
                 float* __restrict__ out)
{
    __shared__ float2 eMh_s[32][64];   // ex2(Mhn) rowsets 0..7, thread-private
    __shared__ float2 eMh8_s[4][32];   // rowset 8 (row 16), per (warp, template)
    __shared__ float2 C2sh[16 * 33];   // EKC-scaled C2, per template (stride 33)
    __shared__ int   idxs[2][17];
    __shared__ float xn2s[2][17];
    __shared__ float fgw_s[2][16];

    const int tid  = threadIdx.x;
    const int w    = tid >> 5;
    const int lane = tid & 31;
    const int node = blockIdx.x * 2 + w;
    const int t    = lane >> 1;
    const int l    = lane & 1;
    const int mate_src = lane & ~1;
    const bool l0 = (l == 0);

    if (lane < 17) {
        int id = lane ? __ldg(&dst[node * 16 + lane - 1]) : node;
        idxs[w][lane] = id;
        xn2s[w][lane] = g_xn2[id];
    }
    __syncwarp();

    const float EKC = 7.21347520444482f;   // 5 * log2(e)
    const float HF  = -0.5f * EKC;
    const float2 ONE = bc2(1.f);

    // Own C2 rows 4l..4l+3; cc2; write EKC-scaled C2 once per block (warp 0)
    {
        float2 C2h[4][4];
        #pragma unroll
        for (int j = 0; j < 4; j++) {
            const float4* p = (const float4*)&g_C2s[(t * 8 + 4 * l + j) * 8];
            float4 a = __ldg(&p[0]), b = __ldg(&p[1]);
            C2h[j][0] = make_float2(a.x, a.y); C2h[j][1] = make_float2(a.z, a.w);
            C2h[j][2] = make_float2(b.x, b.y); C2h[j][3] = make_float2(b.z, b.w);
        }
        float2 cc2f[4];
        #pragma unroll
        for (int c = 0; c < 4; c++) {
            float2 a = mul2(C2h[0][c], C2h[0][c]);
            a = fma2(C2h[1][c], C2h[1][c], a);
            a = fma2(C2h[2][c], C2h[2][c], a);
            a = fma2(C2h[3][c], C2h[3][c], a);
            a.x += __shfl_xor_sync(FULLMASK, a.x, 1);
            a.y += __shfl_xor_sync(FULLMASK, a.y, 1);
            cc2f[c] = make_float2(a.x * 0.125f, a.y * 0.125f);
        }
        if (w == 0) {
            #pragma unroll
            for (int j = 0; j < 4; j++)
                #pragma unroll
                for (int c = 0; c < 4; c++)
                    C2sh[t * 33 + (4 * l + j) * 4 + c] = mul2(C2h[j][c], bc2(EKC));
        }

        // eMh = ex2(Mhn), Mhn = -(M + c1h + cc2) * 0.5 * EKC
        float2 tf2f[4];
        float4 ta = *(const float4*)&g_tf2[t * 8];
        float4 tb = *(const float4*)&g_tf2[t * 8 + 4];
        tf2f[0] = make_float2(ta.x, ta.y); tf2f[1] = make_float2(ta.z, ta.w);
        tf2f[2] = make_float2(tb.x, tb.y); tf2f[3] = make_float2(tb.z, tb.w);
        #pragma unroll
        for (int r = 0; r < 9; r++) {
            int row = (r < 8) ? 2 * r + l : 16;
            int id = idxs[w][row];
            float n2 = xn2s[w][row];
            float4 g0 = __ldg((const float4*)&g_G[id * 128 + t * 8]);
            float4 g1 = __ldg((const float4*)&g_G[id * 128 + t * 8 + 4]);
            float gg[8] = {g0.x,g0.y,g0.z,g0.w,g1.x,g1.y,g1.z,g1.w};
            float c1h = (r == 0 && l0) ? (16.f / 17.f) : (1.f / 17.f);
            #pragma unroll
            for (int c = 0; c < 4; c++) {
                float mx = (n2 + tf2f[c].x - 2.f * gg[2*c])   * (1.f / 128.f);
                float my = (n2 + tf2f[c].y - 2.f * gg[2*c+1]) * (1.f / 128.f);
                float2 e = make_float2(ex2((mx + c1h + cc2f[c].x) * HF),
                                       ex2((my + c1h + cc2f[c].y) * HF));
                if (r < 8) eMh_s[r * 4 + c][tid] = e;
                else if (l0) eMh8_s[c][w * 16 + t] = e;
            }
        }
    }
    __syncthreads();

    const float2* __restrict__ c2l = &C2sh[t * 33 + l * 16];

    // State: u kept pre-duplicated in packed pairs (u2) to avoid per-use MOVs
    float2 K[9][4], vr[4], u2[9];
    #pragma unroll
    for (int r = 0; r < 9; r++) {
        float init = (r == 8) ? (l0 ? 1.f / 136.f : 0.f) : (1.f / 136.f);
        #pragma unroll
        for (int c = 0; c < 4; c++) K[r][c] = bc2(init);
        u2[r] = ONE;
    }
    #pragma unroll
    for (int c = 0; c < 4; c++) vr[c] = ONE;

    #pragma unroll 1
    for (int outer = 0; outer < 5; outer++) {
        // P in place: K <- u * K * v
        #pragma unroll
        for (int r = 0; r < 9; r++) {
            #pragma unroll
            for (int c = 0; c < 4; c++)
                K[r][c] = mul2(mul2(K[r][c], vr[c]), u2[r]);
        }
        float2 pA0f[4], pArf[4];
        compute_pA(K, c2l, l, mate_src, pA0f, pArf);

        // K <- P * eMh * (row0 ratio); column scale absorbed into v-init
        #pragma unroll
        for (int c = 0; c < 4; c++) {
            float2 epr, rfx;
            epr.x = ex2(pArf[c].x);
            epr.y = ex2(pArf[c].y);
            rfx.x = ex2(pA0f[c].x - pArf[c].x);
            rfx.y = ex2(pA0f[c].y - pArf[c].y);
            if (!l0) rfx = ONE;
            K[0][c] = mul2(mul2(K[0][c], eMh_s[c][tid]), rfx);
            #pragma unroll
            for (int r = 1; r < 8; r++)
                K[r][c] = mul2(K[r][c], eMh_s[r * 4 + c][tid]);
            K[8][c] = mul2(K[8][c], eMh8_s[c][w * 16 + t]);   // lane1: 0 * x = 0
            vr[c] = epr;
        }

        // Sinkhorn. Epsilon ONLY on r==8 (lane 1's zero row -> rcp(0)=inf).
        #pragma unroll 1
        for (int inner = 0; inner < 10; inner++) {
            #pragma unroll
            for (int r = 0; r < 9; r++) {
                float2 d0 = mul2(K[r][0], vr[0]);
                float2 d1 = mul2(K[r][1], vr[1]);
                d0 = fma2(K[r][2], vr[2], d0);
                d1 = fma2(K[r][3], vr[3], d1);
                d0 = add2(d0, d1);
                float den = d0.x + d0.y;
                if (r == 8) den += 1e-30f;
                float uu = rcpf(den);
                u2[r] = make_float2(uu, uu);
            }
            #pragma unroll
            for (int c = 0; c < 4; c++) {
                float2 pa = mul2(K[0][c], u2[0]);
                float2 pb = mul2(K[1][c], u2[1]);
                pa = fma2(K[2][c], u2[2], pa);
                pb = fma2(K[3][c], u2[3], pb);
                pa = fma2(K[4][c], u2[4], pa);
                pb = fma2(K[5][c], u2[5], pb);
                pa = fma2(K[6][c], u2[6], pa);
                pb = fma2(K[7][c], u2[7], pb);
                pa = fma2(K[8][c], u2[8], pa);
                pa = add2(pa, pb);
                pa.x += __shfl_xor_sync(FULLMASK, pa.x, 1);
                pa.y += __shfl_xor_sync(FULLMASK, pa.y, 1);
                vr[c].x = rcpf(pa.x);
                vr[c].y = rcpf(pa.y);
            }
        }
        // fold the h*p telescoping constant (1/8) into v
        #pragma unroll
        for (int c = 0; c < 4; c++) vr[c] = mul2(vr[c], bc2(0.125f));
    }

    // ---- Final: P in place, recompute Mhn, fgw = -(1/EKC) sum((Mhn+pA).*P) ----
    #pragma unroll
    for (int r = 0; r < 9; r++) {
        #pragma unroll
        for (int c = 0; c < 4; c++)
            K[r][c] = mul2(mul2(K[r][c], vr[c]), u2[r]);
    }
    {
        float2 pA0f[4], pArf[4];
        compute_pA(K, c2l, l, mate_src, pA0f, pArf);

        // cc2 from EKC-scaled C2sh: (1/8)/EKC^2 * sum over all 8 rows
        float2 cc2f[4];
        const float CSC = 0.125f / (EKC * EKC);
        #pragma unroll
        for (int c = 0; c < 4; c++) {
            float2 a = mul2(c2l[c], c2l[c]);
            a = fma2(c2l[4 + c],  c2l[4 + c],  a);
            a = fma2(c2l[8 + c],  c2l[8 + c],  a);
            a = fma2(c2l[12 + c], c2l[12 + c], a);
            a.x += __shfl_xor_sync(FULLMASK, a.x, 1);
            a.y += __shfl_xor_sync(FULLMASK, a.y, 1);
            cc2f[c] = make_float2(a.x * CSC, a.y * CSC);
        }
        float2 tf2f[4];
        float4 ta = *(const float4*)&g_tf2[t * 8];
        float4 tb = *(const float4*)&g_tf2[t * 8 + 4];
        tf2f[0] = make_float2(ta.x, ta.y); tf2f[1] = make_float2(ta.z, ta.w);
        tf2f[2] = make_float2(tb.x, tb.y); tf2f[3] = make_float2(tb.z, tb.w);

        float2 accv = bc2(0.f);
        #pragma unroll
        for (int r = 0; r < 9; r++) {
            int row = (r < 8) ? 2 * r + l : 16;
            int id = idxs[w][row];
            float n2 = xn2s[w][row];
            float4 g0 = __ldg((const float4*)&g_G[id * 128 + t * 8]);
            float4 g1 = __ldg((const float4*)&g_G[id * 128 + t * 8 + 4]);
            float gg[8] = {g0.x,g0.y,g0.z,g0.w,g1.x,g1.y,g1.z,g1.w};
            float c1h = (r == 0 && l0) ? (16.f / 17.f) : (1.f / 17.f);
            const float2* pa = (r == 0 && l0) ? pA0f : pArf;
            #pragma unroll
            for (int c = 0; c < 4; c++) {
                float mx = (n2 + tf2f[c].x - 2.f * gg[2*c])   * (1.f / 128.f);
                float my = (n2 + tf2f[c].y - 2.f * gg[2*c+1]) * (1.f / 128.f);
                float2 g = make_float2((mx + c1h + cc2f[c].x) * HF + pa[c].x,
                                       (my + c1h + cc2f[c].y) * HF + pa[c].y);
                accv = fma2(g, K[r][c], accv);
            }
        }
        float loc = accv.x + accv.y;
        loc += __shfl_xor_sync(FULLMASK, loc, 1);
        if (l0) fgw_s[w][t] = loc * (-1.f / EKC);
    }
    __syncwarp();

    if (lane < 8) {
        float o = __ldg(&bvec[lane]);
        #pragma unroll
        for (int tt = 0; tt < 16; tt++)
            o += fgw_s[w][tt] * __ldg(&Wm[tt * 8 + lane]);
        out[node * 8 + lane] = o;
    }
}

extern "C" void kernel_launch(void* const* d_in, const int* in_sizes, int n_in,
                              void* d_out, int out_size) {
    const float* x   = (const float*)d_in[0];
    const int*   ei  = (const int*)d_in[1];
    const float* lt  = (const float*)d_in[2];
    const float* tf  = (const float*)d_in[3];
    const float* Wm  = (const float*)d_in[4];
    const float* bv  = (const float*)d_in[5];
    float* out = (float*)d_out;

    const int N = in_sizes[0] / 128;   // 10000 (even)
    const int* dst = ei + N * 16;

    precompute_kernel<<<(N + 31) / 32, 128>>>(x, lt, tf, N);
    otgnn_fgw_kernel<<<N / 2, 64>>>(dst, Wm, bv, out);
}